// round 13
// baseline (speedup 1.0000x reference)
#include <cuda_runtime.h>
#include <cuda_bf16.h>
#include <cstdint>
#include <math.h>

#define RAYS    8192
#define SAMPLES 256
#define GRIDN   160
#define ACT_SHIFT (-13.815509557964274f)

// ---------------- pair-interleaved layouts ----------------
// word pos within a row: pos(w) = (w & ~7) + 2*(w&3) + ((w>>2)&1)
// so fragment words (kw = 8ks+q, 8ks+q+4) sit adjacent -> one LDS.64.
// Row strides (words) chosen ≡ 8 (mod 32): per 16-lane phase the 64-bit
// bank index (W/2 mod 16) = 4*gid + q + const -> conflict-free LDS.64.
#define W1I_STRIDE 72    // 64 data words + 8 pad
#define W0I_STRIDE 40    // 24 data words + 16 pad
#define X_STRIDE   40    // 24 words (20 data + 4 zero) + 16 pad

#define OFF_W1I  0                        // 128*72*4 = 36864
#define OFF_W0I  36864                    // 128*40*4 = 20480
#define OFF_X    57344                    // 256*40*4 = 40960
#define OFF_B0   98304                    // 512
#define OFF_B1   98816                    // 512
#define OFF_W2P  99328                    // float4[128] = 2048
#define OFF_SCA  101376                   // 1024
#define OFF_SCB  102400                   // 1024
#define OFF_WGT  103424                   // 1024
#define OFF_VEMF 104448                   // 128
#define OFF_V2   104576                   // 64
#define OFF_RED  104640                   // 96
#define SMEM_DYN 104736                   // x2 = 209472 <= 228KB -> 2 CTAs/SM

__device__ __forceinline__ int pairpos(int w) {
    return (w & ~7) + 2 * (w & 3) + ((w >> 2) & 1);
}

__device__ __forceinline__ void mma16816(float& c0, float& c1, float& c2, float& c3,
                                         uint32_t a0, uint32_t a1, uint32_t a2, uint32_t a3,
                                         uint32_t b0, uint32_t b1) {
    asm volatile("mma.sync.aligned.m16n8k16.row.col.f32.bf16.bf16.f32 "
                 "{%0,%1,%2,%3}, {%4,%5,%6,%7}, {%8,%9}, {%0,%1,%2,%3};"
                 : "+f"(c0), "+f"(c1), "+f"(c2), "+f"(c3)
                 : "r"(a0), "r"(a1), "r"(a2), "r"(a3), "r"(b0), "r"(b1));
}

__device__ __forceinline__ uint32_t packbf2(float lo, float hi) {
    __nv_bfloat162 b = __floats2bfloat162_rn(lo, hi);
    return *(uint32_t*)&b;
}

extern "C" __global__ void __launch_bounds__(256, 2)
dvgo_hmma2_kernel(const float* __restrict__ ray_pts,
                  const float* __restrict__ viewdirs,
                  const float* __restrict__ dgrid,
                  const float* __restrict__ k0,
                  const float* __restrict__ w0,
                  const float* __restrict__ b0,
                  const float* __restrict__ w1,
                  const float* __restrict__ b1,
                  const float* __restrict__ w2,
                  const float* __restrict__ b2,
                  float* __restrict__ out)
{
    extern __shared__ char smem[];
    uint32_t* s_w1i = (uint32_t*)(smem + OFF_W1I);
    uint32_t* s_w0i = (uint32_t*)(smem + OFF_W0I);
    uint32_t* s_x   = (uint32_t*)(smem + OFF_X);
    float*    s_b0  = (float*)(smem + OFF_B0);
    float*    s_b1  = (float*)(smem + OFF_B1);
    float4*   s_w2p = (float4*)(smem + OFF_W2P);
    float*    sA    = (float*)(smem + OFF_SCA);
    float*    sB    = (float*)(smem + OFF_SCB);
    float*    s_wgt = (float*)(smem + OFF_WGT);
    float*    s_vf  = (float*)(smem + OFF_VEMF);
    __nv_bfloat162* s_v2 = (__nv_bfloat162*)(smem + OFF_V2);
    float*    s_red = (float*)(smem + OFF_RED);

    const int tid = threadIdx.x;
    const int ray = blockIdx.x;
    const int lane = tid & 31;
    const int warp = tid >> 5;
    const int gid = lane >> 2;
    const int q   = lane & 3;

    // ---------------- stage weights (pair-interleaved bf16x2) ----------------
    // s_w1i[n][pos(w)] = (w1[2w][n], w1[2w+1][n]),  w = kw index 0..63
    for (int i = tid; i < 128 * 64; i += 256) {
        int n = i & 127, w = i >> 7;
        s_w1i[n * W1I_STRIDE + pairpos(w)] =
            packbf2(w1[(2 * w) * 128 + n], w1[(2 * w + 1) * 128 + n]);
    }
    // s_w0i[n][pos(w)] = (w0[2w][n], w0[2w+1][n]), w = 0..23, zero for k >= 39
    for (int i = tid; i < 128 * 24; i += 256) {
        int n = i & 127, w = i >> 7;
        int ka = 2 * w, kb = 2 * w + 1;
        float lo = (ka < 39) ? w0[ka * 128 + n] : 0.0f;
        float hi = (kb < 39) ? w0[kb * 128 + n] : 0.0f;
        s_w0i[n * W0I_STRIDE + pairpos(w)] = packbf2(lo, hi);
    }
    if (tid < 128) {
        s_b0[tid] = b0[tid];
        s_b1[tid] = b1[tid];
        float4 w; w.x = w2[tid * 3]; w.y = w2[tid * 3 + 1]; w.z = w2[tid * 3 + 2]; w.w = 0.0f;
        s_w2p[tid] = w;
    }

    // ---------------- view embedding (per ray) ----------------
    if (tid < 28) {
        float vx = viewdirs[ray * 3 + 0];
        float vy = viewdirs[ray * 3 + 1];
        float vz = viewdirs[ray * 3 + 2];
        float inv = 1.0f / (sqrtf(vx * vx + vy * vy + vz * vz) + 1e-10f);
        float dd[3] = {vx * inv, vy * inv, vz * inv};
        float val;
        if (tid < 3)       val = dd[tid];
        else if (tid < 15) { int m = tid - 3;  val = sinf(dd[m >> 2] * (float)(1 << (m & 3))); }
        else if (tid < 27) { int m = tid - 15; val = cosf(dd[m >> 2] * (float)(1 << (m & 3))); }
        else               val = 0.0f;
        s_vf[tid] = val;
    }

    // ---------------- density trilinear + alpha (fp32, accuracy-critical) ----------------
    const int pidx = (ray * SAMPLES + tid) * 3;
    float px = ray_pts[pidx + 0];
    float py = ray_pts[pidx + 1];
    float pz = ray_pts[pidx + 2];

    float gx = fminf(fmaxf(px, 0.0f), 1.0f) * 159.0f;
    float gy = fminf(fmaxf(py, 0.0f), 1.0f) * 159.0f;
    float gz = fminf(fmaxf(pz, 0.0f), 1.0f) * 159.0f;
    int ix = (int)floorf(gx); ix = max(0, min(ix, 158));
    int iy = (int)floorf(gy); iy = max(0, min(iy, 158));
    int iz = (int)floorf(gz); iz = max(0, min(iz, 158));
    float fx = gx - (float)ix, fy = gy - (float)iy, fz = gz - (float)iz;

    const int base = (ix * GRIDN + iy) * GRIDN + iz;
    const float wx0 = 1.0f - fx, wx1 = fx;
    const float wy0 = 1.0f - fy, wy1 = fy;
    const float wz0 = 1.0f - fz, wz1 = fz;
    const int XS = GRIDN * GRIDN;

    float d000 = __ldg(dgrid + base);
    float d001 = __ldg(dgrid + base + 1);
    float d010 = __ldg(dgrid + base + GRIDN);
    float d011 = __ldg(dgrid + base + GRIDN + 1);
    float d100 = __ldg(dgrid + base + XS);
    float d101 = __ldg(dgrid + base + XS + 1);
    float d110 = __ldg(dgrid + base + XS + GRIDN);
    float d111 = __ldg(dgrid + base + XS + GRIDN + 1);

    float den = wx0 * (wy0 * (wz0 * d000 + wz1 * d001) +
                       wy1 * (wz0 * d010 + wz1 * d011)) +
                wx1 * (wy0 * (wz0 * d100 + wz1 * d101) +
                       wy1 * (wz0 * d110 + wz1 * d111));

    float e = expf(den + ACT_SHIFT);
    float alpha = 1.0f - 1.0f / sqrtf(1.0f + e);
    float t = 1.0f - alpha + 1e-10f;
    sA[tid] = t;
    __syncthreads();
    if (tid < 14) s_v2[tid] = __floats2bfloat162_rn(s_vf[2 * tid], s_vf[2 * tid + 1]);

    // ---------------- cumprod scan ----------------
    float v = t;
    float* cur = sA;
    float* nxt = sB;
    #pragma unroll
    for (int off = 1; off < SAMPLES; off <<= 1) {
        if (tid >= off) v *= cur[tid - off];
        nxt[tid] = v;
        __syncthreads();
        float* tmp = cur; cur = nxt; nxt = tmp;
    }
    float T_excl    = (tid == 0) ? 1.0f : cur[tid - 1];
    float ainv_last = cur[SAMPLES - 1];
    s_wgt[tid] = alpha * T_excl;

    // ---------------- feature trilinear (12 ch) ----------------
    const float4* k0v = (const float4*)k0;
    float ft[12];
    #pragma unroll
    for (int c = 0; c < 12; c++) ft[c] = 0.0f;
    #pragma unroll
    for (int cx = 0; cx < 2; cx++) {
        float wxa = cx ? wx1 : wx0;
        #pragma unroll
        for (int cy = 0; cy < 2; cy++) {
            float wxy = wxa * (cy ? wy1 : wy0);
            #pragma unroll
            for (int cz = 0; cz < 2; cz++) {
                float wc = wxy * (cz ? wz1 : wz0);
                int idx = base + cx * XS + cy * GRIDN + cz;
                int b3 = idx * 3;
                float4 qa = __ldg(k0v + b3);
                float4 qb = __ldg(k0v + b3 + 1);
                float4 qc = __ldg(k0v + b3 + 2);
                ft[0]  += wc * qa.x;  ft[1]  += wc * qa.y;
                ft[2]  += wc * qa.z;  ft[3]  += wc * qa.w;
                ft[4]  += wc * qb.x;  ft[5]  += wc * qb.y;
                ft[6]  += wc * qb.z;  ft[7]  += wc * qb.w;
                ft[8]  += wc * qc.x;  ft[9]  += wc * qc.y;
                ft[10] += wc * qc.z;  ft[11] += wc * qc.w;
            }
        }
    }

    // ---------------- stage x row (pair-interleaved; w=20..23 zero) ----------------
    {
        uint32_t xv[20];
        #pragma unroll
        for (int p = 0; p < 6; p++) xv[p] = packbf2(ft[2 * p], ft[2 * p + 1]);
        #pragma unroll
        for (int p = 0; p < 14; p++) {
            __nv_bfloat162 b = s_v2[p];
            xv[6 + p] = *(uint32_t*)&b;
        }
        uint32_t* xrow = s_x + tid * X_STRIDE;
        #pragma unroll
        for (int w = 0; w < 24; w++)
            xrow[pairpos(w)] = (w < 20) ? xv[w] : 0u;
    }
    __syncthreads();

    // ---------------- MLP via HMMA: warp owns 32 samples = 2 m16 tiles ----------------
    // B fragments are loaded ONCE per n-tile and reused for both m-tiles:
    // halves B LDS traffic and gives 2 independent accumulation chains.
    const float B2x = __ldg(b2 + 0), B2y = __ldg(b2 + 1), B2z = __ldg(b2 + 2);
    const int wbase = warp * 32;
    const int r0t[2] = { wbase + gid, wbase + 16 + gid };

    // A0 fragments for both tiles (K=48: 3 k-steps)
    uint32_t A0[2][3][4];
    #pragma unroll
    for (int mt = 0; mt < 2; mt++) {
        #pragma unroll
        for (int ks = 0; ks < 3; ks++) {
            uint2 va = *(const uint2*)(s_x + r0t[mt] * X_STRIDE + ks * 8 + 2 * q);
            uint2 vb = *(const uint2*)(s_x + (r0t[mt] + 8) * X_STRIDE + ks * 8 + 2 * q);
            A0[mt][ks][0] = va.x; A0[mt][ks][2] = va.y;
            A0[mt][ks][1] = vb.x; A0[mt][ks][3] = vb.y;
        }
    }

    // Layer0 -> A1 fragments for both tiles (in-register relu+pack, C==A layout)
    uint32_t A1[2][8][4];
    #pragma unroll
    for (int j = 0; j < 16; j++) {
        const int col = 8 * j + 2 * q;
        const int n   = 8 * j + gid;
        float2 bb = *(const float2*)&s_b0[col];
        float c0[2], c1[2], c2[2], c3[2];
        #pragma unroll
        for (int mt = 0; mt < 2; mt++) { c0[mt] = bb.x; c1[mt] = bb.y; c2[mt] = bb.x; c3[mt] = bb.y; }
        #pragma unroll
        for (int ks = 0; ks < 3; ks++) {
            uint2 b2f = *(const uint2*)(s_w0i + n * W0I_STRIDE + ks * 8 + 2 * q);
            #pragma unroll
            for (int mt = 0; mt < 2; mt++)
                mma16816(c0[mt], c1[mt], c2[mt], c3[mt],
                         A0[mt][ks][0], A0[mt][ks][1], A0[mt][ks][2], A0[mt][ks][3],
                         b2f.x, b2f.y);
        }
        const int ks1 = j >> 1;
        const int sl  = (j & 1) ? 2 : 0;
        #pragma unroll
        for (int mt = 0; mt < 2; mt++) {
            A1[mt][ks1][sl]     = packbf2(fmaxf(c0[mt], 0.0f), fmaxf(c1[mt], 0.0f));
            A1[mt][ks1][sl + 1] = packbf2(fmaxf(c2[mt], 0.0f), fmaxf(c3[mt], 0.0f));
        }
    }

    // Layer1 (K=128) + fused layer2 epilogue; B shared across tiles
    float rs[2][6];
    #pragma unroll
    for (int mt = 0; mt < 2; mt++)
        #pragma unroll
        for (int c = 0; c < 6; c++) rs[mt][c] = 0.0f;

    #pragma unroll
    for (int j2 = 0; j2 < 16; j2++) {
        const int col = 8 * j2 + 2 * q;
        const int n   = 8 * j2 + gid;
        float2 bb = *(const float2*)&s_b1[col];
        float c0[2], c1[2], c2[2], c3[2];
        #pragma unroll
        for (int mt = 0; mt < 2; mt++) { c0[mt] = bb.x; c1[mt] = bb.y; c2[mt] = bb.x; c3[mt] = bb.y; }
        #pragma unroll
        for (int ks = 0; ks < 8; ks++) {
            uint2 b2f = *(const uint2*)(s_w1i + n * W1I_STRIDE + ks * 8 + 2 * q);
            #pragma unroll
            for (int mt = 0; mt < 2; mt++)
                mma16816(c0[mt], c1[mt], c2[mt], c3[mt],
                         A1[mt][ks][0], A1[mt][ks][1], A1[mt][ks][2], A1[mt][ks][3],
                         b2f.x, b2f.y);
        }
        float4 wA = s_w2p[col];
        float4 wB = s_w2p[col + 1];
        #pragma unroll
        for (int mt = 0; mt < 2; mt++) {
            float a0 = fmaxf(c0[mt], 0.0f), a1 = fmaxf(c1[mt], 0.0f);
            float a2 = fmaxf(c2[mt], 0.0f), a3 = fmaxf(c3[mt], 0.0f);
            rs[mt][0] += a0 * wA.x + a1 * wB.x;
            rs[mt][1] += a0 * wA.y + a1 * wB.y;
            rs[mt][2] += a0 * wA.z + a1 * wB.z;
            rs[mt][3] += a2 * wA.x + a3 * wB.x;
            rs[mt][4] += a2 * wA.y + a3 * wB.y;
            rs[mt][5] += a2 * wA.z + a3 * wB.z;
        }
    }

    // quad reduction + sigmoid + weighting
    float osum0 = 0.0f, osum1 = 0.0f, osum2 = 0.0f;
    #pragma unroll
    for (int mt = 0; mt < 2; mt++) {
        #pragma unroll
        for (int c = 0; c < 6; c++) {
            #pragma unroll
            for (int off = 1; off < 4; off <<= 1)
                rs[mt][c] += __shfl_xor_sync(0xffffffffu, rs[mt][c], off);
        }
        if (q == 0) {
            float wg0 = s_wgt[r0t[mt]], wg1 = s_wgt[r0t[mt] + 8];
            osum0 += wg0 * (1.0f / (1.0f + expf(-(rs[mt][0] + B2x))))
                   + wg1 * (1.0f / (1.0f + expf(-(rs[mt][3] + B2x))));
            osum1 += wg0 * (1.0f / (1.0f + expf(-(rs[mt][1] + B2y))))
                   + wg1 * (1.0f / (1.0f + expf(-(rs[mt][4] + B2y))));
            osum2 += wg0 * (1.0f / (1.0f + expf(-(rs[mt][2] + B2z))))
                   + wg1 * (1.0f / (1.0f + expf(-(rs[mt][5] + B2z))));
        }
    }

    // ---------------- reduce over warp, then block ----------------
    #pragma unroll
    for (int s = 16; s > 0; s >>= 1) {
        osum0 += __shfl_down_sync(0xffffffffu, osum0, s);
        osum1 += __shfl_down_sync(0xffffffffu, osum1, s);
        osum2 += __shfl_down_sync(0xffffffffu, osum2, s);
    }
    if (lane == 0) {
        s_red[warp * 3 + 0] = osum0;
        s_red[warp * 3 + 1] = osum1;
        s_red[warp * 3 + 2] = osum2;
    }
    __syncthreads();
    if (tid == 0) {
        float a0 = 0.0f, a1 = 0.0f, a2 = 0.0f;
        #pragma unroll
        for (int w = 0; w < 8; w++) {
            a0 += s_red[w * 3 + 0];
            a1 += s_red[w * 3 + 1];
            a2 += s_red[w * 3 + 2];
        }
        out[ray * 3 + 0] = a0 + ainv_last;
        out[ray * 3 + 1] = a1 + ainv_last;
        out[ray * 3 + 2] = a2 + ainv_last;
    }
}

extern "C" void kernel_launch(void* const* d_in, const int* in_sizes, int n_in,
                              void* d_out, int out_size)
{
    const float* ray_pts  = (const float*)d_in[0];
    const float* viewdirs = (const float*)d_in[1];
    const float* dgrid    = (const float*)d_in[2];
    const float* k0       = (const float*)d_in[3];
    const float* w0       = (const float*)d_in[4];
    const float* b0       = (const float*)d_in[5];
    const float* w1       = (const float*)d_in[6];
    const float* b1       = (const float*)d_in[7];
    const float* w2       = (const float*)d_in[8];
    const float* b2       = (const float*)d_in[9];
    float* out = (float*)d_out;

    cudaFuncSetAttribute(dvgo_hmma2_kernel,
                         cudaFuncAttributeMaxDynamicSharedMemorySize, SMEM_DYN);
    dvgo_hmma2_kernel<<<RAYS, 256, SMEM_DYN>>>(
        ray_pts, viewdirs, dgrid, k0, w0, b0, w1, b1, w2, b2, out);
}

// round 17
// speedup vs baseline: 1.0196x; 1.0196x over previous
#include <cuda_runtime.h>
#include <cuda_bf16.h>
#include <cstdint>
#include <math.h>

#define RAYS    8192
#define SAMPLES 256
#define GRIDN   160
#define ACT_SHIFT (-13.815509557964274f)

// ---------------- pair-interleaved layouts ----------------
// word pos within row: pos(w) = (w & ~7) + 2*(w&3) + ((w>>2)&1)
// fragment words (8ks+q, 8ks+q+4) sit adjacent -> one LDS.64.
// Row strides (words) ≡ 8 (mod 32): 64-bit bank = 4*gid+q (+const) per
// 16-lane phase -> conflict-free LDS.64.
#define W1I_STRIDE 72    // 64 data + 8 pad
#define W0I_STRIDE 40    // 24 data + 16 pad
#define X_STRIDE   40    // 24 (20 data + 4 zero) + 16 pad

#define OFF_W1I  0                        // 128*72*4 = 36864
#define OFF_W0I  36864                    // 128*40*4 = 20480
#define OFF_X    57344                    // 256*40*4 = 40960
#define OFF_B0   98304                    // 512
#define OFF_B1   98816                    // 512
#define OFF_W2P  99328                    // float4[128] = 2048
#define OFF_SCA  101376                   // 1024
#define OFF_SCB  102400                   // 1024
#define OFF_WGT  103424                   // 1024
#define OFF_VEMF 104448                   // 128
#define OFF_V2   104576                   // 64
#define OFF_RED  104640                   // 96
#define SMEM_DYN 104736                   // x2 = 209472 <= 228KB -> 2 CTAs/SM

__device__ __forceinline__ int pairpos(int w) {
    return (w & ~7) + 2 * (w & 3) + ((w >> 2) & 1);
}

__device__ __forceinline__ void mma16816(float& c0, float& c1, float& c2, float& c3,
                                         uint32_t a0, uint32_t a1, uint32_t a2, uint32_t a3,
                                         uint32_t b0, uint32_t b1) {
    asm volatile("mma.sync.aligned.m16n8k16.row.col.f32.bf16.bf16.f32 "
                 "{%0,%1,%2,%3}, {%4,%5,%6,%7}, {%8,%9}, {%0,%1,%2,%3};"
                 : "+f"(c0), "+f"(c1), "+f"(c2), "+f"(c3)
                 : "r"(a0), "r"(a1), "r"(a2), "r"(a3), "r"(b0), "r"(b1));
}

__device__ __forceinline__ uint32_t packbf2(float lo, float hi) {
    __nv_bfloat162 b = __floats2bfloat162_rn(lo, hi);
    return *(uint32_t*)&b;
}

extern "C" __global__ void __launch_bounds__(256, 2)
dvgo_hmma3_kernel(const float* __restrict__ ray_pts,
                  const float* __restrict__ viewdirs,
                  const float* __restrict__ dgrid,
                  const float* __restrict__ k0,
                  const float* __restrict__ w0,
                  const float* __restrict__ b0,
                  const float* __restrict__ w1,
                  const float* __restrict__ b1,
                  const float* __restrict__ w2,
                  const float* __restrict__ b2,
                  float* __restrict__ out)
{
    extern __shared__ char smem[];
    uint32_t* s_w1i = (uint32_t*)(smem + OFF_W1I);
    uint32_t* s_w0i = (uint32_t*)(smem + OFF_W0I);
    uint32_t* s_x   = (uint32_t*)(smem + OFF_X);
    float*    s_b0  = (float*)(smem + OFF_B0);
    float*    s_b1  = (float*)(smem + OFF_B1);
    float4*   s_w2p = (float4*)(smem + OFF_W2P);
    float*    sA    = (float*)(smem + OFF_SCA);
    float*    sB    = (float*)(smem + OFF_SCB);
    float*    s_wgt = (float*)(smem + OFF_WGT);
    float*    s_vf  = (float*)(smem + OFF_VEMF);
    __nv_bfloat162* s_v2 = (__nv_bfloat162*)(smem + OFF_V2);
    float*    s_red = (float*)(smem + OFF_RED);

    const int tid = threadIdx.x;
    const int ray = blockIdx.x;
    const int lane = tid & 31;
    const int warp = tid >> 5;
    const int gid = lane >> 2;
    const int q   = lane & 3;

    // ---------------- stage weights (pair-interleaved bf16x2) ----------------
    for (int i = tid; i < 128 * 64; i += 256) {
        int n = i & 127, w = i >> 7;
        s_w1i[n * W1I_STRIDE + pairpos(w)] =
            packbf2(w1[(2 * w) * 128 + n], w1[(2 * w + 1) * 128 + n]);
    }
    for (int i = tid; i < 128 * 24; i += 256) {
        int n = i & 127, w = i >> 7;
        int ka = 2 * w, kb = 2 * w + 1;
        float lo = (ka < 39) ? w0[ka * 128 + n] : 0.0f;
        float hi = (kb < 39) ? w0[kb * 128 + n] : 0.0f;
        s_w0i[n * W0I_STRIDE + pairpos(w)] = packbf2(lo, hi);
    }
    if (tid < 128) {
        s_b0[tid] = b0[tid];
        s_b1[tid] = b1[tid];
        float4 w; w.x = w2[tid * 3]; w.y = w2[tid * 3 + 1]; w.z = w2[tid * 3 + 2]; w.w = 0.0f;
        s_w2p[tid] = w;
    }

    // ---------------- view embedding (per ray) ----------------
    if (tid < 28) {
        float vx = viewdirs[ray * 3 + 0];
        float vy = viewdirs[ray * 3 + 1];
        float vz = viewdirs[ray * 3 + 2];
        float inv = 1.0f / (sqrtf(vx * vx + vy * vy + vz * vz) + 1e-10f);
        float dd[3] = {vx * inv, vy * inv, vz * inv};
        float val;
        if (tid < 3)       val = dd[tid];
        else if (tid < 15) { int m = tid - 3;  val = sinf(dd[m >> 2] * (float)(1 << (m & 3))); }
        else if (tid < 27) { int m = tid - 15; val = cosf(dd[m >> 2] * (float)(1 << (m & 3))); }
        else               val = 0.0f;
        s_vf[tid] = val;
    }

    // ---------------- density trilinear + alpha (fp32, accuracy-critical) ----------------
    const int pidx = (ray * SAMPLES + tid) * 3;
    float px = ray_pts[pidx + 0];
    float py = ray_pts[pidx + 1];
    float pz = ray_pts[pidx + 2];

    float gx = fminf(fmaxf(px, 0.0f), 1.0f) * 159.0f;
    float gy = fminf(fmaxf(py, 0.0f), 1.0f) * 159.0f;
    float gz = fminf(fmaxf(pz, 0.0f), 1.0f) * 159.0f;
    int ix = (int)floorf(gx); ix = max(0, min(ix, 158));
    int iy = (int)floorf(gy); iy = max(0, min(iy, 158));
    int iz = (int)floorf(gz); iz = max(0, min(iz, 158));
    float fx = gx - (float)ix, fy = gy - (float)iy, fz = gz - (float)iz;

    const int base = (ix * GRIDN + iy) * GRIDN + iz;
    const float wx0 = 1.0f - fx, wx1 = fx;
    const float wy0 = 1.0f - fy, wy1 = fy;
    const float wz0 = 1.0f - fz, wz1 = fz;
    const int XS = GRIDN * GRIDN;

    float d000 = __ldg(dgrid + base);
    float d001 = __ldg(dgrid + base + 1);
    float d010 = __ldg(dgrid + base + GRIDN);
    float d011 = __ldg(dgrid + base + GRIDN + 1);
    float d100 = __ldg(dgrid + base + XS);
    float d101 = __ldg(dgrid + base + XS + 1);
    float d110 = __ldg(dgrid + base + XS + GRIDN);
    float d111 = __ldg(dgrid + base + XS + GRIDN + 1);

    float den = wx0 * (wy0 * (wz0 * d000 + wz1 * d001) +
                       wy1 * (wz0 * d010 + wz1 * d011)) +
                wx1 * (wy0 * (wz0 * d100 + wz1 * d101) +
                       wy1 * (wz0 * d110 + wz1 * d111));

    float e = expf(den + ACT_SHIFT);
    float alpha = 1.0f - 1.0f / sqrtf(1.0f + e);
    float t = 1.0f - alpha + 1e-10f;
    sA[tid] = t;
    __syncthreads();
    if (tid < 14) s_v2[tid] = __floats2bfloat162_rn(s_vf[2 * tid], s_vf[2 * tid + 1]);

    // ---------------- cumprod scan ----------------
    float v = t;
    float* cur = sA;
    float* nxt = sB;
    #pragma unroll
    for (int off = 1; off < SAMPLES; off <<= 1) {
        if (tid >= off) v *= cur[tid - off];
        nxt[tid] = v;
        __syncthreads();
        float* tmp = cur; cur = nxt; nxt = tmp;
    }
    float T_excl    = (tid == 0) ? 1.0f : cur[tid - 1];
    float ainv_last = cur[SAMPLES - 1];
    s_wgt[tid] = alpha * T_excl;

    // ---------------- feature trilinear (12 ch) ----------------
    const float4* k0v = (const float4*)k0;
    float ft[12];
    #pragma unroll
    for (int c = 0; c < 12; c++) ft[c] = 0.0f;
    #pragma unroll
    for (int cx = 0; cx < 2; cx++) {
        float wxa = cx ? wx1 : wx0;
        #pragma unroll
        for (int cy = 0; cy < 2; cy++) {
            float wxy = wxa * (cy ? wy1 : wy0);
            #pragma unroll
            for (int cz = 0; cz < 2; cz++) {
                float wc = wxy * (cz ? wz1 : wz0);
                int idx = base + cx * XS + cy * GRIDN + cz;
                int b3 = idx * 3;
                float4 qa = __ldg(k0v + b3);
                float4 qb = __ldg(k0v + b3 + 1);
                float4 qc = __ldg(k0v + b3 + 2);
                ft[0]  += wc * qa.x;  ft[1]  += wc * qa.y;
                ft[2]  += wc * qa.z;  ft[3]  += wc * qa.w;
                ft[4]  += wc * qb.x;  ft[5]  += wc * qb.y;
                ft[6]  += wc * qb.z;  ft[7]  += wc * qb.w;
                ft[8]  += wc * qc.x;  ft[9]  += wc * qc.y;
                ft[10] += wc * qc.z;  ft[11] += wc * qc.w;
            }
        }
    }

    // ---------------- stage x row (pair-interleaved; w=20..23 zero) ----------------
    {
        uint32_t xv[20];
        #pragma unroll
        for (int p = 0; p < 6; p++) xv[p] = packbf2(ft[2 * p], ft[2 * p + 1]);
        #pragma unroll
        for (int p = 0; p < 14; p++) {
            __nv_bfloat162 b = s_v2[p];
            xv[6 + p] = *(uint32_t*)&b;
        }
        uint32_t* xrow = s_x + tid * X_STRIDE;
        #pragma unroll
        for (int w = 0; w < 24; w++)
            xrow[pairpos(w)] = (w < 20) ? xv[w] : 0u;
    }
    __syncthreads();

    // ---------------- MLP via HMMA: per warp 32 samples = 2 sequential m16 tiles ----------------
    // (R11 structure: one m-tile in flight -> A1 = 32 regs, no spills.
    //  Improvement: all fragment loads are single conflict-free LDS.64.)
    const float B2x = __ldg(b2 + 0), B2y = __ldg(b2 + 1), B2z = __ldg(b2 + 2);
    float osum0 = 0.0f, osum1 = 0.0f, osum2 = 0.0f;
    const int wbase = warp * 32;

    #pragma unroll
    for (int mt = 0; mt < 2; mt++) {
        const int r0 = wbase + mt * 16 + gid;
        const int r1 = r0 + 8;

        // A0 fragments (K=48: 3 k-steps), LDS.64 each
        uint32_t A0[3][4];
        #pragma unroll
        for (int ks = 0; ks < 3; ks++) {
            uint2 va = *(const uint2*)(s_x + r0 * X_STRIDE + ks * 8 + 2 * q);
            uint2 vb = *(const uint2*)(s_x + r1 * X_STRIDE + ks * 8 + 2 * q);
            A0[ks][0] = va.x; A0[ks][2] = va.y;
            A0[ks][1] = vb.x; A0[ks][3] = vb.y;
        }

        // Layer0: 16 n8-tiles; C fragments convert in-register to layer1 A fragments.
        uint32_t A1[8][4];
        #pragma unroll
        for (int j = 0; j < 16; j++) {
            const int col = 8 * j + 2 * q;
            const int n   = 8 * j + gid;
            float2 bb = *(const float2*)&s_b0[col];
            float c0 = bb.x, c1 = bb.y, c2 = bb.x, c3 = bb.y;
            #pragma unroll
            for (int ks = 0; ks < 3; ks++) {
                uint2 bf = *(const uint2*)(s_w0i + n * W0I_STRIDE + ks * 8 + 2 * q);
                mma16816(c0, c1, c2, c3,
                         A0[ks][0], A0[ks][1], A0[ks][2], A0[ks][3], bf.x, bf.y);
            }
            uint32_t lo = packbf2(fmaxf(c0, 0.0f), fmaxf(c1, 0.0f));  // row r0
            uint32_t hi = packbf2(fmaxf(c2, 0.0f), fmaxf(c3, 0.0f));  // row r1
            const int ks1 = j >> 1;
            if ((j & 1) == 0) { A1[ks1][0] = lo; A1[ks1][1] = hi; }
            else              { A1[ks1][2] = lo; A1[ks1][3] = hi; }
        }

        // Layer1 (K=128, 8 k-steps) + fused layer2 epilogue
        float rs00 = 0.0f, rs01 = 0.0f, rs02 = 0.0f;
        float rs10 = 0.0f, rs11 = 0.0f, rs12 = 0.0f;
        #pragma unroll
        for (int j2 = 0; j2 < 16; j2++) {
            const int col = 8 * j2 + 2 * q;
            const int n   = 8 * j2 + gid;
            float2 bb = *(const float2*)&s_b1[col];
            float c0 = bb.x, c1 = bb.y, c2 = bb.x, c3 = bb.y;
            #pragma unroll
            for (int ks = 0; ks < 8; ks++) {
                uint2 bf = *(const uint2*)(s_w1i + n * W1I_STRIDE + ks * 8 + 2 * q);
                mma16816(c0, c1, c2, c3,
                         A1[ks][0], A1[ks][1], A1[ks][2], A1[ks][3], bf.x, bf.y);
            }
            float4 wA = s_w2p[col];
            float4 wB = s_w2p[col + 1];
            float a0 = fmaxf(c0, 0.0f), a1 = fmaxf(c1, 0.0f);
            float a2 = fmaxf(c2, 0.0f), a3 = fmaxf(c3, 0.0f);
            rs00 += a0 * wA.x + a1 * wB.x;
            rs01 += a0 * wA.y + a1 * wB.y;
            rs02 += a0 * wA.z + a1 * wB.z;
            rs10 += a2 * wA.x + a3 * wB.x;
            rs11 += a2 * wA.y + a3 * wB.y;
            rs12 += a2 * wA.z + a3 * wB.z;
        }

        // quad reduction (cols spread over 4 quad lanes)
        #pragma unroll
        for (int off = 1; off < 4; off <<= 1) {
            rs00 += __shfl_xor_sync(0xffffffffu, rs00, off);
            rs01 += __shfl_xor_sync(0xffffffffu, rs01, off);
            rs02 += __shfl_xor_sync(0xffffffffu, rs02, off);
            rs10 += __shfl_xor_sync(0xffffffffu, rs10, off);
            rs11 += __shfl_xor_sync(0xffffffffu, rs11, off);
            rs12 += __shfl_xor_sync(0xffffffffu, rs12, off);
        }

        if (q == 0) {
            float wg0 = s_wgt[r0], wg1 = s_wgt[r1];
            osum0 += wg0 * (1.0f / (1.0f + expf(-(rs00 + B2x))))
                   + wg1 * (1.0f / (1.0f + expf(-(rs10 + B2x))));
            osum1 += wg0 * (1.0f / (1.0f + expf(-(rs01 + B2y))))
                   + wg1 * (1.0f / (1.0f + expf(-(rs11 + B2y))));
            osum2 += wg0 * (1.0f / (1.0f + expf(-(rs02 + B2z))))
                   + wg1 * (1.0f / (1.0f + expf(-(rs12 + B2z))));
        }
    }

    // ---------------- reduce over warp, then block ----------------
    #pragma unroll
    for (int s = 16; s > 0; s >>= 1) {
        osum0 += __shfl_down_sync(0xffffffffu, osum0, s);
        osum1 += __shfl_down_sync(0xffffffffu, osum1, s);
        osum2 += __shfl_down_sync(0xffffffffu, osum2, s);
    }
    if (lane == 0) {
        s_red[warp * 3 + 0] = osum0;
        s_red[warp * 3 + 1] = osum1;
        s_red[warp * 3 + 2] = osum2;
    }
    __syncthreads();
    if (tid == 0) {
        float a0 = 0.0f, a1 = 0.0f, a2 = 0.0f;
        #pragma unroll
        for (int w = 0; w < 8; w++) {
            a0 += s_red[w * 3 + 0];
            a1 += s_red[w * 3 + 1];
            a2 += s_red[w * 3 + 2];
        }
        out[ray * 3 + 0] = a0 + ainv_last;
        out[ray * 3 + 1] = a1 + ainv_last;
        out[ray * 3 + 2] = a2 + ainv_last;
    }
}

extern "C" void kernel_launch(void* const* d_in, const int* in_sizes, int n_in,
                              void* d_out, int out_size)
{
    const float* ray_pts  = (const float*)d_in[0];
    const float* viewdirs = (const float*)d_in[1];
    const float* dgrid    = (const float*)d_in[2];
    const float* k0       = (const float*)d_in[3];
    const float* w0       = (const float*)d_in[4];
    const float* b0       = (const float*)d_in[5];
    const float* w1       = (const float*)d_in[6];
    const float* b1       = (const float*)d_in[7];
    const float* w2       = (const float*)d_in[8];
    const float* b2       = (const float*)d_in[9];
    float* out = (float*)d_out;

    cudaFuncSetAttribute(dvgo_hmma3_kernel,
                         cudaFuncAttributeMaxDynamicSharedMemorySize, SMEM_DYN);
    dvgo_hmma3_kernel<<<RAYS, 256, SMEM_DYN>>>(
        ray_pts, viewdirs, dgrid, k0, w0, b0, w1, b1, w2, b2, out);
}